// round 6
// baseline (speedup 1.0000x reference)
#include <cuda_runtime.h>
#include <cuda_bf16.h>
#include <cstdint>

// Problem constants (fixed by the dataset)
#define NN 50000
#define EE 800000

// ---------------------------------------------------------------------------
// Device-global scratch (no allocations allowed)
// ---------------------------------------------------------------------------
__device__ float4 g_s1 [NN * 12];   // s1 (post-LN) per node, 48 floats
__device__ float4 g_V1 [NN * 12];   // V1_pre (unscaled) per node, 48 floats
__device__ float4 g_pre[NN * 68];   // per-node gather record, 272 floats:
                                    // [0:96) VhG_pre (gve_Wh[:, :16] @ V1_pre), h-major xyz
                                    // [96:192) VhE_pre (ge_Wh[:, :16] @ V1_pre)
                                    // [192:240) P_gve = gve_Wm_w[:, :48] @ s1
                                    // [240:272) P_ge  = ge_Wm_w[:, :48] @ s1
__device__ float4 g_upd[NN * 24];   // segment-sum accumulator -> later su_ln|Vu_pre
__device__ float  g_sumsq[2];
__device__ float  g_scale[2];
__device__ int    g_idx64;

// ---------------------------------------------------------------------------
// idx dtype detection: if edge_idx is int64, every odd int32 word (high word
// of values < 50000) is zero. Random int32 indices make that impossible.
// ---------------------------------------------------------------------------
__global__ void k_detect(const int* __restrict__ idx) {
    if (threadIdx.x == 0 && blockIdx.x == 0) {
        int allz = 1;
        for (int i = 1; i < 128; i += 2) allz &= (idx[i] == 0);
        g_idx64 = allz;
    }
}

__global__ void k_zero() {
    int i = blockIdx.x * blockDim.x + threadIdx.x;
    int st = gridDim.x * blockDim.x;
    float4 z = make_float4(0.f, 0.f, 0.f, 0.f);
    for (int t = i; t < NN * 24; t += st) g_upd[t] = z;
    if (i == 0) { g_sumsq[0] = 0.f; g_sumsq[1] = 0.f; }
}

// ---------------------------------------------------------------------------
// Kernel 1: per-node GVP(gv) + residual + LN; V1_pre; precomputes for edges.
// One warp per node; 4 warps / 128-thread block (static smem < 48 KB).
// ---------------------------------------------------------------------------
struct NodeWS {
    float4 V0[16];
    float4 Vh[32];
    float  x[80];     // [s0(48) | sh(32)]
    float  s1[48];
    float4 V1[16];
};

__global__ __launch_bounds__(128) void k_node1(
    const float* __restrict__ nodes,
    const float* __restrict__ Wh,   // gv_Wh   (32,16)
    const float* __restrict__ Wmu,  // gv_Wmu  (16,32)
    const float* __restrict__ Wm,   // gv_Wm_w (48,80)
    const float* __restrict__ Wb,   // gv_Wm_b (48)
    const float* __restrict__ lng, const float* __restrict__ lnb,
    const float* __restrict__ gveWh,  // (32,32)
    const float* __restrict__ geWh,   // (32,32)
    const float* __restrict__ gveWm,  // (48,112)
    const float* __restrict__ geWm)   // (32,112)
{
    __shared__ float sWhT[16 * 32];   // [v*32+h] = gv_Wh[h][v]
    __shared__ float sMuT[32 * 16];   // [h*16+m] = gv_Wmu[m][h]
    __shared__ float sWmT[80 * 48];   // [k*48+o] = gv_Wm_w[o][k]
    __shared__ float sB[48], sG[48], sBe[48];
    __shared__ float sWhG[16 * 32];   // [v*32+h] = gve_Wh[h][v], v<16
    __shared__ float sWhE[16 * 32];   // ge_Wh
    __shared__ float sPmG[48 * 48];   // [k*48+o] = gve_Wm_w[o][k], k<48
    __shared__ float sPmE[48 * 32];   // [k*32+o] = ge_Wm_w[o][k],  k<48
    __shared__ NodeWS ws[4];

    int tid = threadIdx.x;
    for (int i = tid; i < 512; i += 128) { int v = i >> 5, h = i & 31; sWhT[i] = Wh[h * 16 + v]; }
    for (int i = tid; i < 512; i += 128) { int h = i >> 4, m = i & 15; sMuT[i] = Wmu[m * 32 + h]; }
    for (int i = tid; i < 3840; i += 128) { int k = i / 48, o = i % 48; sWmT[i] = Wm[o * 80 + k]; }
    for (int i = tid; i < 48; i += 128) { sB[i] = Wb[i]; sG[i] = lng[i]; sBe[i] = lnb[i]; }
    for (int i = tid; i < 512; i += 128) {
        int v = i >> 5, h = i & 31;
        sWhG[i] = gveWh[h * 32 + v]; sWhE[i] = geWh[h * 32 + v];
    }
    for (int i = tid; i < 2304; i += 128) { int k = i / 48, o = i % 48; sPmG[i] = gveWm[o * 112 + k]; }
    for (int i = tid; i < 1536; i += 128) { int k = i / 32, o = i % 32; sPmE[i] = geWm[o * 112 + k]; }
    __syncthreads();

    int warp = tid >> 5, lane = tid & 31, o1 = (lane & 15) + 32;
    NodeWS& W = ws[warp];
    int gw = blockIdx.x * 4 + warp, nw = gridDim.x * 4;
    float lsum = 0.f;
    float* s1g = (float*)g_s1;
    float* v1g = (float*)g_V1;
    float* pre = (float*)g_pre;

    for (int n = gw; n < NN; n += nw) {
        const float* row = nodes + (size_t)n * 96;
        for (int t = lane; t < 96; t += 32) {
            float v = row[t];
            if (t < 48) W.x[t] = v;
            else { int j = t - 48; ((float*)&W.V0[0])[(j / 3) * 4 + (j % 3)] = v; }
        }
        __syncwarp();

        // Vh[h] = gv_Wh @ V0  (lane = h)
        float a0 = 0.f, a1 = 0.f, a2 = 0.f;
#pragma unroll
        for (int v = 0; v < 16; v++) {
            float w = sWhT[v * 32 + lane]; float4 c = W.V0[v];
            a0 = fmaf(w, c.x, a0); a1 = fmaf(w, c.y, a1); a2 = fmaf(w, c.z, a2);
        }
        W.Vh[lane] = make_float4(a0, a1, a2, 0.f);
        W.x[48 + lane] = sqrtf(a0 * a0 + a1 * a1 + a2 * a2);
        __syncwarp();

        // Vmu[m] = gv_Wmu @ Vh  (lanes 0..15)
        float u0 = 0.f, u1 = 0.f, u2 = 0.f;
        if (lane < 16) {
#pragma unroll
            for (int h = 0; h < 32; h++) {
                float w = sMuT[h * 16 + lane]; float4 vh = W.Vh[h];
                u0 = fmaf(w, vh.x, u0); u1 = fmaf(w, vh.y, u1); u2 = fmaf(w, vh.z, u2);
            }
        }

        // MLP: out o = lane (0..31) and o1 = lane+32 (lanes 0..15)
        float acc0 = sB[lane], acc1 = sB[o1];
#pragma unroll 8
        for (int k = 0; k < 80; k++) {
            float xv = W.x[k];
            acc0 = fmaf(sWmT[k * 48 + lane], xv, acc0);
            acc1 = fmaf(sWmT[k * 48 + o1],  xv, acc1);
        }
        float su0 = fmaxf(acc0, 0.f) + W.x[lane];
        float su1 = fmaxf(acc1, 0.f) + W.x[o1];

        // LayerNorm over 48
        float s = su0 + ((lane < 16) ? su1 : 0.f);
#pragma unroll
        for (int off = 16; off; off >>= 1) s += __shfl_xor_sync(0xffffffffu, s, off);
        float mean = s * (1.f / 48.f);
        float d0 = su0 - mean, d1 = su1 - mean;
        float q = d0 * d0 + ((lane < 16) ? d1 * d1 : 0.f);
#pragma unroll
        for (int off = 16; off; off >>= 1) q += __shfl_xor_sync(0xffffffffu, q, off);
        float rstd = rsqrtf(q * (1.f / 48.f) + 1e-5f);
        float s1a = d0 * rstd * sG[lane] + sBe[lane];
        float s1b = d1 * rstd * sG[o1]  + sBe[o1];
        W.s1[lane] = s1a; s1g[(size_t)n * 48 + lane] = s1a;
        if (lane < 16) { W.s1[o1] = s1b; s1g[(size_t)n * 48 + o1] = s1b; }

        // V1_pre = ||Vmu||*Vmu + V0  (lanes 0..15), accumulate global sumsq
        if (lane < 16) {
            float vn = sqrtf(u0 * u0 + u1 * u1 + u2 * u2);
            float4 c = W.V0[lane];
            float p0 = fmaf(vn, u0, c.x), p1 = fmaf(vn, u1, c.y), p2 = fmaf(vn, u2, c.z);
            lsum += p0 * p0 + p1 * p1 + p2 * p2;
            W.V1[lane] = make_float4(p0, p1, p2, 0.f);
            v1g[(size_t)n * 48 + 3 * lane + 0] = p0;
            v1g[(size_t)n * 48 + 3 * lane + 1] = p1;
            v1g[(size_t)n * 48 + 3 * lane + 2] = p2;
        }
        __syncwarp();

        // Precompute VhG_pre / VhE_pre  (lane = h)
        float gg0 = 0.f, gg1 = 0.f, gg2 = 0.f, ee0 = 0.f, ee1 = 0.f, ee2 = 0.f;
#pragma unroll
        for (int v = 0; v < 16; v++) {
            float4 p = W.V1[v];
            float wg = sWhG[v * 32 + lane];
            gg0 = fmaf(wg, p.x, gg0); gg1 = fmaf(wg, p.y, gg1); gg2 = fmaf(wg, p.z, gg2);
            float we = sWhE[v * 32 + lane];
            ee0 = fmaf(we, p.x, ee0); ee1 = fmaf(we, p.y, ee1); ee2 = fmaf(we, p.z, ee2);
        }
        float* pr = pre + (size_t)n * 272;
        pr[lane * 3 + 0] = gg0; pr[lane * 3 + 1] = gg1; pr[lane * 3 + 2] = gg2;
        pr[96 + lane * 3 + 0] = ee0; pr[96 + lane * 3 + 1] = ee1; pr[96 + lane * 3 + 2] = ee2;

        // Precompute P_gve (48 outs) / P_ge (32 outs)
        float pg0 = 0.f, pg1 = 0.f, pe0 = 0.f;
#pragma unroll 8
        for (int k = 0; k < 48; k++) {
            float sv = W.s1[k];
            pg0 = fmaf(sPmG[k * 48 + lane], sv, pg0);
            pg1 = fmaf(sPmG[k * 48 + o1],  sv, pg1);
            pe0 = fmaf(sPmE[k * 32 + lane], sv, pe0);
        }
        pr[192 + lane] = pg0;
        if (lane < 16) pr[192 + o1] = pg1;
        pr[240 + lane] = pe0;
        __syncwarp();
    }
#pragma unroll
    for (int off = 16; off; off >>= 1) lsum += __shfl_xor_sync(0xffffffffu, lsum, off);
    if (lane == 0) atomicAdd(&g_sumsq[0], lsum);
}

// scale = 1/sqrt(frob/16), frob = sqrt(sumsq)
template <int I>
__global__ void k_scale() {
    g_scale[I] = rsqrtf(sqrtf(g_sumsq[I]) * (1.f / 16.f));
}

// ---------------------------------------------------------------------------
// Kernel 2: per-edge double GVP (gve + ge). Warp per edge, grid-stride.
// ---------------------------------------------------------------------------
struct EdgeWS {
    float  rec[272];     // gathered per-node record
    float  erow[80];     // edge_attrs row: [s_e(32) | V_e(48)]
    float4 Vhg[32];
    float4 Vhe[32];
    float  shg[32], she[32];
    float  hij[96];      // [ms(48) | mV(48)]
    float  ehij[80];     // [es(32) | eV(48)]
};

__global__ __launch_bounds__(128) void k_edge(
    const float* __restrict__ edges,
    const void*  __restrict__ eidx,
    const float* __restrict__ gveWh, const float* __restrict__ gveMu,
    const float* __restrict__ gveWm, const float* __restrict__ gveWb,
    const float* __restrict__ geWh,  const float* __restrict__ geMu,
    const float* __restrict__ geWm,  const float* __restrict__ geWb,
    float* __restrict__ out_e)
{
    __shared__ float sWhG[512], sWhE[512];       // [v*32+h] = Wh[h][16+v]
    __shared__ float sMuG[512], sMuE[512];       // [h*16+m] = Wmu[m][h]
    __shared__ float sWmG[64 * 48];              // [k*48+o] = gve_Wm_w[o][48+k]
    __shared__ float sWmE[64 * 32];              // [k*32+o] = ge_Wm_w[o][48+k]
    __shared__ float sBG[48], sBE[32];
    __shared__ EdgeWS ws[4];

    int tid = threadIdx.x;
    for (int i = tid; i < 512; i += 128) {
        int v = i >> 5, h = i & 31;
        sWhG[i] = gveWh[h * 32 + 16 + v]; sWhE[i] = geWh[h * 32 + 16 + v];
    }
    for (int i = tid; i < 512; i += 128) {
        int h = i >> 4, m = i & 15;
        sMuG[i] = gveMu[m * 32 + h]; sMuE[i] = geMu[m * 32 + h];
    }
    for (int i = tid; i < 3072; i += 128) { int k = i / 48, o = i % 48; sWmG[i] = gveWm[o * 112 + 48 + k]; }
    for (int i = tid; i < 2048; i += 128) { int k = i / 32, o = i % 32; sWmE[i] = geWm[o * 112 + 48 + k]; }
    for (int i = tid; i < 48; i += 128) sBG[i] = gveWb[i];
    for (int i = tid; i < 32; i += 128) sBE[i] = geWb[i];
    __syncthreads();

    int warp = tid >> 5, lane = tid & 31, o1 = (lane & 15) + 32;
    EdgeWS& W = ws[warp];
    int gw = blockIdx.x * 4 + warp, nw = gridDim.x * 4;
    const float sc0 = g_scale[0];
    const int is64 = g_idx64;
    const int* idx32 = (const int*)eidx;
    const long long* idx64 = (const long long*)eidx;
    float* updf = (float*)g_upd;
    const float4* pre4 = (const float4*)g_pre;
    const float4* edges4 = (const float4*)edges;

    for (int e = gw; e < EE; e += nw) {
        int src, dst;
        if (is64) { src = (int)idx64[e]; dst = (int)idx64[EE + e]; }
        else      { src = idx32[e];      dst = idx32[EE + e]; }

        const float4* pr = pre4 + (size_t)dst * 68;
        for (int t = lane; t < 68; t += 32) ((float4*)W.rec)[t] = pr[t];
        if (lane < 20) ((float4*)W.erow)[lane] = edges4[(size_t)e * 20 + lane];
        __syncwarp();

        // Vh for both branches (lane = h): precomputed node part (scaled) + edge part
        float g0 = sc0 * W.rec[lane * 3 + 0], g1 = sc0 * W.rec[lane * 3 + 1], g2 = sc0 * W.rec[lane * 3 + 2];
        float f0 = sc0 * W.rec[96 + lane * 3 + 0], f1 = sc0 * W.rec[96 + lane * 3 + 1], f2 = sc0 * W.rec[96 + lane * 3 + 2];
#pragma unroll
        for (int v = 0; v < 16; v++) {
            float vx = W.erow[32 + 3 * v], vy = W.erow[33 + 3 * v], vz = W.erow[34 + 3 * v];
            float wg = sWhG[v * 32 + lane];
            g0 = fmaf(wg, vx, g0); g1 = fmaf(wg, vy, g1); g2 = fmaf(wg, vz, g2);
            float we = sWhE[v * 32 + lane];
            f0 = fmaf(we, vx, f0); f1 = fmaf(we, vy, f1); f2 = fmaf(we, vz, f2);
        }
        W.Vhg[lane] = make_float4(g0, g1, g2, 0.f); W.shg[lane] = sqrtf(g0 * g0 + g1 * g1 + g2 * g2);
        W.Vhe[lane] = make_float4(f0, f1, f2, 0.f); W.she[lane] = sqrtf(f0 * f0 + f1 * f1 + f2 * f2);
        __syncwarp();

        // Vmu + vector outputs (lanes 0..15)
        if (lane < 16) {
            float ug0 = 0.f, ug1 = 0.f, ug2 = 0.f, ue0 = 0.f, ue1 = 0.f, ue2 = 0.f;
#pragma unroll
            for (int h = 0; h < 32; h++) {
                float4 a = W.Vhg[h]; float wg = sMuG[h * 16 + lane];
                ug0 = fmaf(wg, a.x, ug0); ug1 = fmaf(wg, a.y, ug1); ug2 = fmaf(wg, a.z, ug2);
                float4 b = W.Vhe[h]; float we = sMuE[h * 16 + lane];
                ue0 = fmaf(we, b.x, ue0); ue1 = fmaf(we, b.y, ue1); ue2 = fmaf(we, b.z, ue2);
            }
            float ng = sqrtf(ug0 * ug0 + ug1 * ug1 + ug2 * ug2);
            W.hij[48 + 3 * lane + 0] = ng * ug0;
            W.hij[48 + 3 * lane + 1] = ng * ug1;
            W.hij[48 + 3 * lane + 2] = ng * ug2;
            float ne = sqrtf(ue0 * ue0 + ue1 * ue1 + ue2 * ue2);
            W.ehij[32 + 3 * lane + 0] = ne * ue0;
            W.ehij[32 + 3 * lane + 1] = ne * ue1;
            W.ehij[32 + 3 * lane + 2] = ne * ue2;
        }

        // Scalar MLPs: ms (48 outs), es (32 outs); node part comes from P.
        float m0 = W.rec[192 + lane] + sBG[lane];
        float m1 = W.rec[192 + o1]  + sBG[o1];
        float e0 = W.rec[240 + lane] + sBE[lane];
#pragma unroll 8
        for (int k = 0; k < 32; k++) {
            float xs = W.erow[k];  // s_e
            m0 = fmaf(sWmG[k * 48 + lane], xs, m0);
            m1 = fmaf(sWmG[k * 48 + o1],  xs, m1);
            e0 = fmaf(sWmE[k * 32 + lane], xs, e0);
        }
#pragma unroll 8
        for (int k = 0; k < 32; k++) {
            float xg = W.shg[k], xe = W.she[k];
            m0 = fmaf(sWmG[(32 + k) * 48 + lane], xg, m0);
            m1 = fmaf(sWmG[(32 + k) * 48 + o1],  xg, m1);
            e0 = fmaf(sWmE[(32 + k) * 32 + lane], xe, e0);
        }
        W.hij[lane] = fmaxf(m0, 0.f);
        if (lane < 16) W.hij[o1] = fmaxf(m1, 0.f);
        W.ehij[lane] = fmaxf(e0, 0.f);
        __syncwarp();

        // Scatter hij into segment-sum accumulator (vector atomics, sm_90+)
        if (lane < 24) {
            float4 v = ((float4*)W.hij)[lane];
            atomicAdd((float4*)(updf + (size_t)src * 96) + lane, v);
        }
        // Store edge output hij_e
        if (lane < 20) {
            ((float4*)(out_e + (size_t)e * 80))[lane] = ((float4*)W.ehij)[lane];
        }
        __syncwarp();
    }
}

// ---------------------------------------------------------------------------
// Kernel 3: per-node finalize pass 1: su = LN(upd/30 + s1); Vu_pre = upd/30 +
// V1_pre*sc0; accumulate sumsq1. Results written in-place into g_upd.
// ---------------------------------------------------------------------------
__global__ __launch_bounds__(256) void k_node2(
    const float* __restrict__ lng, const float* __restrict__ lnb)
{
    int tid = threadIdx.x, warp = tid >> 5, lane = tid & 31, o1 = (lane & 15) + 32;
    int gw = blockIdx.x * 8 + warp, nw = gridDim.x * 8;
    float lsum = 0.f;
    const float inv30 = 1.f / 30.f;
    const float sc0 = g_scale[0];
    float* upd = (float*)g_upd;
    const float* s1g = (const float*)g_s1;
    const float* v1g = (const float*)g_V1;

    for (int n = gw; n < NN; n += nw) {
        size_t b = (size_t)n * 96, bs = (size_t)n * 48;
        float su0 = upd[b + lane] * inv30 + s1g[bs + lane];
        float su1 = upd[b + o1]  * inv30 + s1g[bs + o1];
        float s = su0 + ((lane < 16) ? su1 : 0.f);
#pragma unroll
        for (int off = 16; off; off >>= 1) s += __shfl_xor_sync(0xffffffffu, s, off);
        float mean = s * (1.f / 48.f);
        float d0 = su0 - mean, d1 = su1 - mean;
        float q = d0 * d0 + ((lane < 16) ? d1 * d1 : 0.f);
#pragma unroll
        for (int off = 16; off; off >>= 1) q += __shfl_xor_sync(0xffffffffu, q, off);
        float rstd = rsqrtf(q * (1.f / 48.f) + 1e-5f);
        upd[b + lane] = d0 * rstd * __ldg(&lng[lane]) + __ldg(&lnb[lane]);
        if (lane < 16) upd[b + o1] = d1 * rstd * __ldg(&lng[o1]) + __ldg(&lnb[o1]);

        float v0 = upd[b + 48 + lane] * inv30 + v1g[bs + lane] * sc0;
        float v1 = upd[b + 48 + o1]  * inv30 + v1g[bs + o1]  * sc0;
        lsum += v0 * v0 + ((lane < 16) ? v1 * v1 : 0.f);
        upd[b + 48 + lane] = v0;
        if (lane < 16) upd[b + 48 + o1] = v1;
    }
#pragma unroll
    for (int off = 16; off; off >>= 1) lsum += __shfl_xor_sync(0xffffffffu, lsum, off);
    if (lane == 0) atomicAdd(&g_sumsq[1], lsum);
}

// ---------------------------------------------------------------------------
// Kernel 4: final node output = node2 + node_update, elementwise float4.
// ---------------------------------------------------------------------------
__global__ void k_node3(float* __restrict__ out) {
    int i = blockIdx.x * blockDim.x + threadIdx.x;
    int st = gridDim.x * blockDim.x;
    const float sc0 = g_scale[0], sc1 = g_scale[1];
    float4* out4 = (float4*)out;
    for (int t = i; t < NN * 24; t += st) {
        int n = t / 24, q = t - n * 24;
        float4 r = g_upd[t];
        float4 o;
        if (q < 12) {
            float4 s = g_s1[n * 12 + q];
            o = make_float4(s.x + r.x, s.y + r.y, s.z + r.z, s.w + r.w);
        } else {
            float4 v = g_V1[n * 12 + (q - 12)];
            o = make_float4(fmaf(v.x, sc0, r.x * sc1), fmaf(v.y, sc0, r.y * sc1),
                            fmaf(v.z, sc0, r.z * sc1), fmaf(v.w, sc0, r.w * sc1));
        }
        out4[t] = o;
    }
}

// ---------------------------------------------------------------------------
// Launch: inputs resolved by element count; ambiguous sizes by relative order
// (gv_* before gve_* before ge_* before ln_g before ln_b — holds for both
// setup_inputs dict order and reference signature order).
// ---------------------------------------------------------------------------
extern "C" void kernel_launch(void* const* d_in, const int* in_sizes, int n_in,
                              void* d_out, int out_size) {
    const float *nodes = 0, *edges = 0;
    const void* eidx = 0;
    const float* w512[4]  = {0, 0, 0, 0}; int c512 = 0;   // gv_Wh, gv_Wmu, gve_Wmu, ge_Wmu
    const float* w1024[2] = {0, 0};       int c1024 = 0;  // gve_Wh, ge_Wh
    const float* w48[4]   = {0, 0, 0, 0}; int c48 = 0;    // gv_Wm_b, gve_Wm_b, ln_g, ln_b
    const float *gvWm = 0, *gveWm = 0, *geWm = 0, *geWb = 0;

    for (int i = 0; i < n_in; i++) {
        switch (in_sizes[i]) {
            case 4800000:  nodes = (const float*)d_in[i]; break;
            case 64000000: edges = (const float*)d_in[i]; break;
            case 1600000:  eidx = d_in[i]; break;
            case 512:  if (c512 < 4)  w512[c512++]   = (const float*)d_in[i]; break;
            case 1024: if (c1024 < 2) w1024[c1024++] = (const float*)d_in[i]; break;
            case 48:   if (c48 < 4)   w48[c48++]     = (const float*)d_in[i]; break;
            case 3840: gvWm  = (const float*)d_in[i]; break;
            case 5376: gveWm = (const float*)d_in[i]; break;
            case 3584: geWm  = (const float*)d_in[i]; break;
            case 32:   geWb  = (const float*)d_in[i]; break;
            default: break;
        }
    }
    const float* gvWh  = w512[0];
    const float* gvMu  = w512[1];
    const float* gveMu = w512[2];
    const float* geMu  = w512[3];
    const float* gveWh = w1024[0];
    const float* geWh  = w1024[1];
    const float* gvWb  = w48[0];
    const float* gveWb = w48[1];
    const float* lng   = w48[2];
    const float* lnb   = w48[3];

    float* out   = (float*)d_out;
    float* out_e = out + (size_t)NN * 96;

    k_detect<<<1, 32>>>((const int*)eidx);
    k_zero<<<1184, 256>>>();
    k_node1<<<444, 128>>>(nodes, gvWh, gvMu, gvWm, gvWb, lng, lnb,
                          gveWh, geWh, gveWm, geWm);
    k_scale<0><<<1, 1>>>();
    k_edge<<<592, 128>>>(edges, eidx, gveWh, gveMu, gveWm, gveWb,
                         geWh, geMu, geWm, geWb, out_e);
    k_node2<<<296, 256>>>(lng, lnb);
    k_scale<1><<<1, 1>>>();
    k_node3<<<1184, 256>>>(out);
}

// round 9
// speedup vs baseline: 1.6183x; 1.6183x over previous
#include <cuda_runtime.h>
#include <cuda_bf16.h>
#include <cstdint>

// Problem constants (fixed by the dataset)
#define NN 50000
#define EE 800000

// ---------------------------------------------------------------------------
// Device-global scratch (no allocations allowed)
// ---------------------------------------------------------------------------
__device__ float4 g_s1 [NN * 12];    // s1 (post-LN) per node, 48 floats
__device__ float4 g_V1 [NN * 12];    // V1_pre (unscaled) per node, 48 floats
__device__ float  g_pre[NN * 368];   // per-node record, 368 floats:
                                     // [0:96)    VhG_pre  = gve_Wh[:, :16] @ V1_pre   (h-major xyz)
                                     // [96:192)  VhE_pre  = ge_Wh[:, :16]  @ V1_pre
                                     // [192:240) VmuG_pre = gve_Wmu @ VhG_pre          (m-major xyz)
                                     // [240:288) VmuE_pre = ge_Wmu  @ VhE_pre
                                     // [288:336) P_gve    = gve_Wm_w[:, :48] @ s1
                                     // [336:368) P_ge     = ge_Wm_w[:, :48]  @ s1
__device__ float4 g_upd[NN * 24];    // segment-sum accumulator -> later su_ln|Vu_pre
__device__ float  g_sumsq[2];
__device__ float  g_scale[2];
__device__ int    g_idx64;

// ---------------------------------------------------------------------------
// idx dtype detection: if edge_idx is int64, every odd int32 word (high word
// of values < 50000) is zero. Random int32 indices make that impossible.
// ---------------------------------------------------------------------------
__global__ void k_detect(const int* __restrict__ idx) {
    if (threadIdx.x == 0 && blockIdx.x == 0) {
        int allz = 1;
        for (int i = 1; i < 128; i += 2) allz &= (idx[i] == 0);
        g_idx64 = allz;
    }
}

__global__ void k_zero() {
    int i = blockIdx.x * blockDim.x + threadIdx.x;
    int st = gridDim.x * blockDim.x;
    float4 z = make_float4(0.f, 0.f, 0.f, 0.f);
    for (int t = i; t < NN * 24; t += st) g_upd[t] = z;
    if (i == 0) { g_sumsq[0] = 0.f; g_sumsq[1] = 0.f; }
}

// ---------------------------------------------------------------------------
// Kernel 1: per-node GVP(gv) + residual + LN; V1_pre; edge precomputes.
// One warp per node; 4 warps / 128-thread block.
// ---------------------------------------------------------------------------
struct NodeWS {
    float4 V0[16];
    float  x[80];     // [s0(48) | sh(32)]
    float  s1[48];
    float4 V1[16];
};

__global__ __launch_bounds__(128) void k_node1(
    const float* __restrict__ nodes,
    const float* __restrict__ gvWh,   // (32,16)
    const float* __restrict__ gvMu,   // (16,32)
    const float* __restrict__ gvWm,   // (48,80)
    const float* __restrict__ gvWb,   // (48)
    const float* __restrict__ lng, const float* __restrict__ lnb,
    const float* __restrict__ gveWh,  // (32,32)
    const float* __restrict__ geWh,   // (32,32)
    const float* __restrict__ gveMu,  // (16,32)
    const float* __restrict__ geMu,   // (16,32)
    const float* __restrict__ gveWm,  // (48,112)
    const float* __restrict__ geWm)   // (32,112)
{
    __shared__ float sWhT[16 * 32];   // [v*32+h] = gvWh[h][v]
    __shared__ float sCgv[16 * 16];   // [v*16+m] = (gvMu @ gvWh)[m][v]
    __shared__ float sWmT[80 * 48];   // [k*48+o] = gvWm[o][k]
    __shared__ float sB[48], sG[48], sBe[48];
    __shared__ float sWhGn[16 * 32];  // [v*32+h] = gveWh[h][v], v<16
    __shared__ float sWhEn[16 * 32];  // geWh
    __shared__ float sCN[16 * 32];    // [v*32+c]: c<16 -> (gveMu@gveWh[:, :16])[c][v]
                                      //           c>=16 -> (geMu@geWh[:, :16])[c-16][v]
    __shared__ float sPmG[48 * 48];   // [k*48+o] = gveWm[o][k], k<48
    __shared__ float sPmE[48 * 32];   // [k*32+o] = geWm[o][k],  k<48
    __shared__ NodeWS ws[4];

    int tid = threadIdx.x;
    for (int i = tid; i < 512; i += 128) { int v = i >> 5, h = i & 31; sWhT[i] = gvWh[h * 16 + v]; }
    for (int i = tid; i < 3840; i += 128) { int k = i / 48, o = i % 48; sWmT[i] = gvWm[o * 80 + k]; }
    for (int i = tid; i < 48; i += 128) { sB[i] = gvWb[i]; sG[i] = lng[i]; sBe[i] = lnb[i]; }
    for (int i = tid; i < 512; i += 128) {
        int v = i >> 5, h = i & 31;
        sWhGn[i] = gveWh[h * 32 + v]; sWhEn[i] = geWh[h * 32 + v];
    }
    for (int i = tid; i < 2304; i += 128) { int k = i / 48, o = i % 48; sPmG[i] = gveWm[o * 112 + k]; }
    for (int i = tid; i < 1536; i += 128) { int k = i / 32, o = i % 32; sPmE[i] = geWm[o * 112 + k]; }
    // Precombined 16x16 matrices
    for (int i = tid; i < 256; i += 128) {
        int v = i >> 4, m = i & 15;
        float acc = 0.f;
        for (int h = 0; h < 32; h++) acc = fmaf(gvMu[m * 32 + h], gvWh[h * 16 + v], acc);
        sCgv[i] = acc;
    }
    for (int i = tid; i < 512; i += 128) {
        int v = i >> 5, c = i & 31;
        float acc = 0.f;
        if (c < 16) for (int h = 0; h < 32; h++) acc = fmaf(gveMu[c * 32 + h], gveWh[h * 32 + v], acc);
        else        for (int h = 0; h < 32; h++) acc = fmaf(geMu[(c - 16) * 32 + h], geWh[h * 32 + v], acc);
        sCN[i] = acc;
    }
    __syncthreads();

    int warp = tid >> 5, lane = tid & 31, o1 = (lane & 15) + 32, mo = lane & 15;
    NodeWS& W = ws[warp];
    int gw = blockIdx.x * 4 + warp, nw = gridDim.x * 4;
    float lsum = 0.f;
    float* s1g = (float*)g_s1;
    float* v1g = (float*)g_V1;

    for (int n = gw; n < NN; n += nw) {
        const float* row = nodes + (size_t)n * 96;
        for (int t = lane; t < 96; t += 32) {
            float v = row[t];
            if (t < 48) W.x[t] = v;
            else { int j = t - 48; ((float*)&W.V0[0])[(j / 3) * 4 + (j % 3)] = v; }
        }
        __syncwarp();

        // Vh[h] = gvWh @ V0  (lane = h) -> only its norm needed
        float a0 = 0.f, a1 = 0.f, a2 = 0.f;
#pragma unroll
        for (int v = 0; v < 16; v++) {
            float w = sWhT[v * 32 + lane]; float4 c = W.V0[v];
            a0 = fmaf(w, c.x, a0); a1 = fmaf(w, c.y, a1); a2 = fmaf(w, c.z, a2);
        }
        W.x[48 + lane] = sqrtf(a0 * a0 + a1 * a1 + a2 * a2);

        // Vmu (gv) via precombined Cgv: lanes 0..15, m = lane
        float u0 = 0.f, u1 = 0.f, u2 = 0.f;
        if (lane < 16) {
#pragma unroll
            for (int v = 0; v < 16; v++) {
                float w = sCgv[v * 16 + lane]; float4 c = W.V0[v];
                u0 = fmaf(w, c.x, u0); u1 = fmaf(w, c.y, u1); u2 = fmaf(w, c.z, u2);
            }
        }
        __syncwarp();

        // MLP
        float acc0 = sB[lane], acc1 = sB[o1];
#pragma unroll 8
        for (int k = 0; k < 80; k++) {
            float xv = W.x[k];
            acc0 = fmaf(sWmT[k * 48 + lane], xv, acc0);
            acc1 = fmaf(sWmT[k * 48 + o1],  xv, acc1);
        }
        float su0 = fmaxf(acc0, 0.f) + W.x[lane];
        float su1 = fmaxf(acc1, 0.f) + W.x[o1];

        // LayerNorm over 48
        float s = su0 + ((lane < 16) ? su1 : 0.f);
#pragma unroll
        for (int off = 16; off; off >>= 1) s += __shfl_xor_sync(0xffffffffu, s, off);
        float mean = s * (1.f / 48.f);
        float d0 = su0 - mean, d1 = su1 - mean;
        float q = d0 * d0 + ((lane < 16) ? d1 * d1 : 0.f);
#pragma unroll
        for (int off = 16; off; off >>= 1) q += __shfl_xor_sync(0xffffffffu, q, off);
        float rstd = rsqrtf(q * (1.f / 48.f) + 1e-5f);
        float s1a = d0 * rstd * sG[lane] + sBe[lane];
        float s1b = d1 * rstd * sG[o1]  + sBe[o1];
        W.s1[lane] = s1a; s1g[(size_t)n * 48 + lane] = s1a;
        if (lane < 16) { W.s1[o1] = s1b; s1g[(size_t)n * 48 + o1] = s1b; }

        // V1_pre = ||Vmu||*Vmu + V0  (lanes 0..15), global sumsq
        if (lane < 16) {
            float vn = sqrtf(u0 * u0 + u1 * u1 + u2 * u2);
            float4 c = W.V0[lane];
            float p0 = fmaf(vn, u0, c.x), p1 = fmaf(vn, u1, c.y), p2 = fmaf(vn, u2, c.z);
            lsum += p0 * p0 + p1 * p1 + p2 * p2;
            W.V1[lane] = make_float4(p0, p1, p2, 0.f);
            v1g[(size_t)n * 48 + 3 * lane + 0] = p0;
            v1g[(size_t)n * 48 + 3 * lane + 1] = p1;
            v1g[(size_t)n * 48 + 3 * lane + 2] = p2;
        }
        __syncwarp();

        float* pr = g_pre + (size_t)n * 368;

        // VhG_pre / VhE_pre  (lane = h)
        {
            float gg0 = 0.f, gg1 = 0.f, gg2 = 0.f, ee0 = 0.f, ee1 = 0.f, ee2 = 0.f;
#pragma unroll
            for (int v = 0; v < 16; v++) {
                float4 p = W.V1[v];
                float wg = sWhGn[v * 32 + lane];
                gg0 = fmaf(wg, p.x, gg0); gg1 = fmaf(wg, p.y, gg1); gg2 = fmaf(wg, p.z, gg2);
                float we = sWhEn[v * 32 + lane];
                ee0 = fmaf(we, p.x, ee0); ee1 = fmaf(we, p.y, ee1); ee2 = fmaf(we, p.z, ee2);
            }
            pr[lane * 3 + 0] = gg0; pr[lane * 3 + 1] = gg1; pr[lane * 3 + 2] = gg2;
            pr[96 + lane * 3 + 0] = ee0; pr[96 + lane * 3 + 1] = ee1; pr[96 + lane * 3 + 2] = ee2;
        }

        // VmuG_pre / VmuE_pre mixed: lanes<16 gve (m=lane), lanes>=16 ge (m=lane-16)
        {
            float m0 = 0.f, m1 = 0.f, m2 = 0.f;
#pragma unroll
            for (int v = 0; v < 16; v++) {
                float w = sCN[v * 32 + lane]; float4 p = W.V1[v];
                m0 = fmaf(w, p.x, m0); m1 = fmaf(w, p.y, m1); m2 = fmaf(w, p.z, m2);
            }
            int mb = 192 + ((lane >= 16) ? 48 : 0) + 3 * mo;
            pr[mb + 0] = m0; pr[mb + 1] = m1; pr[mb + 2] = m2;
        }

        // P_gve (48 outs) / P_ge (32 outs)
        {
            float pg0 = 0.f, pg1 = 0.f, pe0 = 0.f;
#pragma unroll 8
            for (int k = 0; k < 48; k++) {
                float sv = W.s1[k];
                pg0 = fmaf(sPmG[k * 48 + lane], sv, pg0);
                pg1 = fmaf(sPmG[k * 48 + o1],  sv, pg1);
                pe0 = fmaf(sPmE[k * 32 + lane], sv, pe0);
            }
            pr[288 + lane] = pg0;
            if (lane < 16) pr[288 + o1] = pg1;
            pr[336 + lane] = pe0;
        }
        __syncwarp();
    }
#pragma unroll
    for (int off = 16; off; off >>= 1) lsum += __shfl_xor_sync(0xffffffffu, lsum, off);
    if (lane == 0) atomicAdd(&g_sumsq[0], lsum);
}

// scale = 1/sqrt(frob/16), frob = sqrt(sumsq)
template <int I>
__global__ void k_scale() {
    g_scale[I] = rsqrtf(sqrtf(g_sumsq[I]) * (1.f / 16.f));
}

// ---------------------------------------------------------------------------
// Kernel 2: per-edge double GVP (gve + ge). Warp per 2 edges, grid-stride.
// Mixed-lane Vmu (lanes<16 gve, lanes>=16 ge), factored through precombined
// 16x16 matrices; MLP with 3 accumulators covering all 80 outputs; weight LDS
// amortized over the edge pair; x-broadcasts pair-packed as float2.
// ---------------------------------------------------------------------------
__global__ __launch_bounds__(128) void k_edge(
    const float* __restrict__ edges,
    const void*  __restrict__ eidx,
    const float* __restrict__ gveWh, const float* __restrict__ gveMu,
    const float* __restrict__ gveWm, const float* __restrict__ gveWb,
    const float* __restrict__ geWh,  const float* __restrict__ geMu,
    const float* __restrict__ geWm,  const float* __restrict__ geWb,
    float* __restrict__ out_e)
{
    __shared__ float  sC [16 * 32];              // [v*32+c]: Cfac mixed (gve|ge)
    __shared__ float  sWA[64 * 32];              // accA weights: gve out c, cols 48+k
    __shared__ float  sWB[64 * 32];              // accB: c<16 gve out 32+c | c>=16 ge out c-16
    __shared__ float  sWC[64 * 32];              // accC: c<16 ge out 16+c | else 0
    __shared__ float  sBA[32], sBB[32], sBC[32];
    __shared__ float2 sSE [4][32];               // s_e pair-packed
    __shared__ float2 sVE [4][48];               // V_e pair-packed (3v+c)
    __shared__ float2 sSHG[4][32], sSHE[4][32];  // sh pair-packed
    __shared__ float  sHIJ[4][2][96];
    __shared__ float  sEH [4][2][80];

    int tid = threadIdx.x;
    // Cfac mixed: c<16 -> (gveMu @ gveWh[:,16:32])[c][v]; c>=16 -> ge version
    for (int i = tid; i < 512; i += 128) {
        int v = i >> 5, c = i & 31;
        float acc = 0.f;
        if (c < 16) for (int h = 0; h < 32; h++) acc = fmaf(gveMu[c * 32 + h], gveWh[h * 32 + 16 + v], acc);
        else        for (int h = 0; h < 32; h++) acc = fmaf(geMu[(c - 16) * 32 + h], geWh[h * 32 + 16 + v], acc);
        sC[i] = acc;
    }
    for (int i = tid; i < 2048; i += 128) {
        int k = i >> 5, c = i & 31;
        sWA[i] = gveWm[c * 112 + 48 + k];
        sWB[i] = (c < 16) ? gveWm[(32 + c) * 112 + 48 + k] : geWm[(c - 16) * 112 + 48 + k];
        sWC[i] = (c < 16) ? geWm[(16 + c) * 112 + 48 + k] : 0.f;
    }
    for (int i = tid; i < 32; i += 128) {
        sBA[i] = gveWb[i];
        sBB[i] = (i < 16) ? gveWb[32 + i] : geWb[i - 16];
        sBC[i] = (i < 16) ? geWb[16 + i] : 0.f;
    }
    __syncthreads();

    int warp = tid >> 5, lane = tid & 31, mo = lane & 15;
    float2* SE = sSE[warp];  float2* VE = sVE[warp];
    float2* SHG = sSHG[warp]; float2* SHE = sSHE[warp];
    float* HIJ0 = sHIJ[warp][0]; float* HIJ1 = sHIJ[warp][1];
    float* EH0  = sEH[warp][0];  float* EH1  = sEH[warp][1];

    // Register-cache Wh edge columns (lane = h)
    float whg[16], whe[16];
#pragma unroll
    for (int v = 0; v < 16; v++) {
        whg[v] = __ldg(&gveWh[lane * 32 + 16 + v]);
        whe[v] = __ldg(&geWh[lane * 32 + 16 + v]);
    }

    int gw = blockIdx.x * 4 + warp, nw = gridDim.x * 4;
    const float sc0 = g_scale[0];
    const int is64 = g_idx64;
    const int* idx32 = (const int*)eidx;
    const long long* idx64 = (const long long*)eidx;
    float* updf = (float*)g_upd;
    const float* pre = g_pre;

    const int mbase = 192 + ((lane >= 16) ? 48 : 0) + 3 * mo;
    const int offA = 288 + lane;
    const int offB = (lane < 16) ? (288 + 32 + lane) : (336 + (lane - 16));
    const int offC = 336 + 16 + mo;  // valid for lane<16 only
    const float2* SB = (lane < 16) ? SHG : SHE;

    for (int p = gw; p < EE / 2; p += nw) {
        int e0 = 2 * p, e1 = e0 + 1;
        int src0, dst0, src1, dst1;
        if (is64) {
            src0 = (int)idx64[e0]; src1 = (int)idx64[e1];
            dst0 = (int)idx64[EE + e0]; dst1 = (int)idx64[EE + e1];
        } else {
            src0 = idx32[e0]; src1 = idx32[e1];
            dst0 = idx32[EE + e0]; dst1 = idx32[EE + e1];
        }

        // Stage edge rows pair-packed
        const float* r0 = edges + (size_t)e0 * 80;
        const float* r1 = edges + (size_t)e1 * 80;
        for (int t = lane; t < 80; t += 32) {
            float a = r0[t], b = r1[t];
            if (t < 32) SE[t] = make_float2(a, b);
            else        VE[t - 32] = make_float2(a, b);
        }

        const float* p0 = pre + (size_t)dst0 * 368;
        const float* p1 = pre + (size_t)dst1 * 368;

        // Vh accumulators, both branches x both edges (lane = h)
        float ga0 = sc0 * p0[3 * lane], ga1 = sc0 * p0[3 * lane + 1], ga2 = sc0 * p0[3 * lane + 2];
        float gb0 = sc0 * p1[3 * lane], gb1 = sc0 * p1[3 * lane + 1], gb2 = sc0 * p1[3 * lane + 2];
        float fa0 = sc0 * p0[96 + 3 * lane], fa1 = sc0 * p0[96 + 3 * lane + 1], fa2 = sc0 * p0[96 + 3 * lane + 2];
        float fb0 = sc0 * p1[96 + 3 * lane], fb1 = sc0 * p1[96 + 3 * lane + 1], fb2 = sc0 * p1[96 + 3 * lane + 2];
        // Vmu accumulators (mixed lanes)
        float ua0 = sc0 * p0[mbase], ua1 = sc0 * p0[mbase + 1], ua2 = sc0 * p0[mbase + 2];
        float ub0 = sc0 * p1[mbase], ub1 = sc0 * p1[mbase + 1], ub2 = sc0 * p1[mbase + 2];
        __syncwarp();

        // Fused Vh + Vmu loop over edge vectors
#pragma unroll
        for (int v = 0; v < 16; v++) {
            float2 vx = VE[3 * v], vy = VE[3 * v + 1], vz = VE[3 * v + 2];
            float wg = whg[v], we = whe[v], cf = sC[v * 32 + lane];
            ga0 = fmaf(wg, vx.x, ga0); ga1 = fmaf(wg, vy.x, ga1); ga2 = fmaf(wg, vz.x, ga2);
            gb0 = fmaf(wg, vx.y, gb0); gb1 = fmaf(wg, vy.y, gb1); gb2 = fmaf(wg, vz.y, gb2);
            fa0 = fmaf(we, vx.x, fa0); fa1 = fmaf(we, vy.x, fa1); fa2 = fmaf(we, vz.x, fa2);
            fb0 = fmaf(we, vx.y, fb0); fb1 = fmaf(we, vy.y, fb1); fb2 = fmaf(we, vz.y, fb2);
            ua0 = fmaf(cf, vx.x, ua0); ua1 = fmaf(cf, vy.x, ua1); ua2 = fmaf(cf, vz.x, ua2);
            ub0 = fmaf(cf, vx.y, ub0); ub1 = fmaf(cf, vy.y, ub1); ub2 = fmaf(cf, vz.y, ub2);
        }

        // Norms -> pair-packed shared
        SHG[lane] = make_float2(sqrtf(ga0 * ga0 + ga1 * ga1 + ga2 * ga2),
                                sqrtf(gb0 * gb0 + gb1 * gb1 + gb2 * gb2));
        SHE[lane] = make_float2(sqrtf(fa0 * fa0 + fa1 * fa1 + fa2 * fa2),
                                sqrtf(fb0 * fb0 + fb1 * fb1 + fb2 * fb2));

        // Vmu output: relu(||Vmu||)*Vmu = ||Vmu||*Vmu (norm >= 0)
        {
            float na = sqrtf(ua0 * ua0 + ua1 * ua1 + ua2 * ua2);
            float nb = sqrtf(ub0 * ub0 + ub1 * ub1 + ub2 * ub2);
            float* h0 = (lane < 16) ? &HIJ0[48 + 3 * mo] : &EH0[32 + 3 * mo];
            float* h1 = (lane < 16) ? &HIJ1[48 + 3 * mo] : &EH1[32 + 3 * mo];
            h0[0] = na * ua0; h0[1] = na * ua1; h0[2] = na * ua2;
            h1[0] = nb * ub0; h1[1] = nb * ub1; h1[2] = nb * ub2;
        }

        // MLP accumulators (node-dependent part gathered + bias)
        float A0 = p0[offA] + sBA[lane], A1 = p1[offA] + sBA[lane];
        float B0 = p0[offB] + sBB[lane], B1 = p1[offB] + sBB[lane];
        float C0 = 0.f, C1 = 0.f;
        if (lane < 16) { C0 = p0[offC] + sBC[lane]; C1 = p1[offC] + sBC[lane]; }
        __syncwarp();

#pragma unroll 8
        for (int k = 0; k < 32; k++) {
            float2 x = SE[k];
            float wA = sWA[k * 32 + lane], wB = sWB[k * 32 + lane], wC = sWC[k * 32 + lane];
            A0 = fmaf(wA, x.x, A0); A1 = fmaf(wA, x.y, A1);
            B0 = fmaf(wB, x.x, B0); B1 = fmaf(wB, x.y, B1);
            C0 = fmaf(wC, x.x, C0); C1 = fmaf(wC, x.y, C1);
        }
#pragma unroll 8
        for (int j = 0; j < 32; j++) {
            float2 xg = SHG[j], xe = SHE[j], xb = SB[j];
            int k = 32 + j;
            float wA = sWA[k * 32 + lane], wB = sWB[k * 32 + lane], wC = sWC[k * 32 + lane];
            A0 = fmaf(wA, xg.x, A0); A1 = fmaf(wA, xg.y, A1);
            B0 = fmaf(wB, xb.x, B0); B1 = fmaf(wB, xb.y, B1);
            C0 = fmaf(wC, xe.x, C0); C1 = fmaf(wC, xe.y, C1);
        }

        // ReLU + scalar staging
        HIJ0[lane] = fmaxf(A0, 0.f); HIJ1[lane] = fmaxf(A1, 0.f);
        if (lane < 16) {
            HIJ0[32 + lane] = fmaxf(B0, 0.f); HIJ1[32 + lane] = fmaxf(B1, 0.f);
            EH0[16 + lane]  = fmaxf(C0, 0.f); EH1[16 + lane]  = fmaxf(C1, 0.f);
        } else {
            EH0[lane - 16] = fmaxf(B0, 0.f); EH1[lane - 16] = fmaxf(B1, 0.f);
        }
        __syncwarp();

        // Scatter hij (vector atomics) + store edge outputs
        if (lane < 24) {
            atomicAdd((float4*)(updf + (size_t)src0 * 96) + lane, ((float4*)HIJ0)[lane]);
            atomicAdd((float4*)(updf + (size_t)src1 * 96) + lane, ((float4*)HIJ1)[lane]);
        }
        if (lane < 20) {
            ((float4*)(out_e + (size_t)e0 * 80))[lane] = ((float4*)EH0)[lane];
            ((float4*)(out_e + (size_t)e1 * 80))[lane] = ((float4*)EH1)[lane];
        }
        __syncwarp();
    }
}

// ---------------------------------------------------------------------------
// Kernel 3: per-node finalize pass 1: su = LN(upd/30 + s1); Vu_pre = upd/30 +
// V1_pre*sc0; accumulate sumsq1. Results written in-place into g_upd.
// ---------------------------------------------------------------------------
__global__ __launch_bounds__(256) void k_node2(
    const float* __restrict__ lng, const float* __restrict__ lnb)
{
    int tid = threadIdx.x, warp = tid >> 5, lane = tid & 31, o1 = (lane & 15) + 32;
    int gw = blockIdx.x * 8 + warp, nw = gridDim.x * 8;
    float lsum = 0.f;
    const float inv30 = 1.f / 30.f;
    const float sc0 = g_scale[0];
    float* upd = (float*)g_upd;
    const float* s1g = (const float*)g_s1;
    const float* v1g = (const float*)g_V1;

    for (int n = gw; n < NN; n += nw) {
        size_t b = (size_t)n * 96, bs = (size_t)n * 48;
        float su0 = upd[b + lane] * inv30 + s1g[bs + lane];
        float su1 = upd[b + o1]  * inv30 + s1g[bs + o1];
        float s = su0 + ((lane < 16) ? su1 : 0.f);
#pragma unroll
        for (int off = 16; off; off >>= 1) s += __shfl_xor_sync(0xffffffffu, s, off);
        float mean = s * (1.f / 48.f);
        float d0 = su0 - mean, d1 = su1 - mean;
        float q = d0 * d0 + ((lane < 16) ? d1 * d1 : 0.f);
#pragma unroll
        for (int off = 16; off; off >>= 1) q += __shfl_xor_sync(0xffffffffu, q, off);
        float rstd = rsqrtf(q * (1.f / 48.f) + 1e-5f);
        upd[b + lane] = d0 * rstd * __ldg(&lng[lane]) + __ldg(&lnb[lane]);
        if (lane < 16) upd[b + o1] = d1 * rstd * __ldg(&lng[o1]) + __ldg(&lnb[o1]);

        float v0 = upd[b + 48 + lane] * inv30 + v1g[bs + lane] * sc0;
        float v1 = upd[b + 48 + o1]  * inv30 + v1g[bs + o1]  * sc0;
        lsum += v0 * v0 + ((lane < 16) ? v1 * v1 : 0.f);
        upd[b + 48 + lane] = v0;
        if (lane < 16) upd[b + 48 + o1] = v1;
    }
#pragma unroll
    for (int off = 16; off; off >>= 1) lsum += __shfl_xor_sync(0xffffffffu, lsum, off);
    if (lane == 0) atomicAdd(&g_sumsq[1], lsum);
}

// ---------------------------------------------------------------------------
// Kernel 4: final node output = node2 + node_update, elementwise float4.
// ---------------------------------------------------------------------------
__global__ void k_node3(float* __restrict__ out) {
    int i = blockIdx.x * blockDim.x + threadIdx.x;
    int st = gridDim.x * blockDim.x;
    const float sc0 = g_scale[0], sc1 = g_scale[1];
    float4* out4 = (float4*)out;
    for (int t = i; t < NN * 24; t += st) {
        int n = t / 24, q = t - n * 24;
        float4 r = g_upd[t];
        float4 o;
        if (q < 12) {
            float4 s = g_s1[n * 12 + q];
            o = make_float4(s.x + r.x, s.y + r.y, s.z + r.z, s.w + r.w);
        } else {
            float4 v = g_V1[n * 12 + (q - 12)];
            o = make_float4(fmaf(v.x, sc0, r.x * sc1), fmaf(v.y, sc0, r.y * sc1),
                            fmaf(v.z, sc0, r.z * sc1), fmaf(v.w, sc0, r.w * sc1));
        }
        out4[t] = o;
    }
}

// ---------------------------------------------------------------------------
// Launch: inputs resolved by element count; ambiguous sizes by relative order
// (gv_* before gve_* before ge_* before ln_g before ln_b).
// ---------------------------------------------------------------------------
extern "C" void kernel_launch(void* const* d_in, const int* in_sizes, int n_in,
                              void* d_out, int out_size) {
    const float *nodes = 0, *edges = 0;
    const void* eidx = 0;
    const float* w512[4]  = {0, 0, 0, 0}; int c512 = 0;   // gv_Wh, gv_Wmu, gve_Wmu, ge_Wmu
    const float* w1024[2] = {0, 0};       int c1024 = 0;  // gve_Wh, ge_Wh
    const float* w48[4]   = {0, 0, 0, 0}; int c48 = 0;    // gv_Wm_b, gve_Wm_b, ln_g, ln_b
    const float *gvWm = 0, *gveWm = 0, *geWm = 0, *geWb = 0;

    for (int i = 0; i < n_in; i++) {
        switch (in_sizes[i]) {
            case 4800000:  nodes = (const float*)d_in[i]; break;
            case 64000000: edges = (const float*)d_in[i]; break;
            case 1600000:  eidx = d_in[i]; break;
            case 512:  if (c512 < 4)  w512[c512++]   = (const float*)d_in[i]; break;
            case 1024: if (c1024 < 2) w1024[c1024++] = (const float*)d_in[i]; break;
            case 48:   if (c48 < 4)   w48[c48++]     = (const float*)d_in[i]; break;
            case 3840: gvWm  = (const float*)d_in[i]; break;
            case 5376: gveWm = (const float*)d_in[i]; break;
            case 3584: geWm  = (const float*)d_in[i]; break;
            case 32:   geWb  = (const float*)d_in[i]; break;
            default: break;
        }
    }
    const float* gvWh  = w512[0];
    const float* gvMu  = w512[1];
    const float* gveMu = w512[2];
    const float* geMu  = w512[3];
    const float* gveWh = w1024[0];
    const float* geWh  = w1024[1];
    const float* gvWb  = w48[0];
    const float* gveWb = w48[1];
    const float* lng   = w48[2];
    const float* lnb   = w48[3];

    float* out   = (float*)d_out;
    float* out_e = out + (size_t)NN * 96;

    k_detect<<<1, 32>>>((const int*)eidx);
    k_zero<<<1184, 256>>>();
    k_node1<<<444, 128>>>(nodes, gvWh, gvMu, gvWm, gvWb, lng, lnb,
                          gveWh, geWh, gveMu, geMu, gveWm, geWm);
    k_scale<0><<<1, 1>>>();
    k_edge<<<592, 128>>>(edges, eidx, gveWh, gveMu, gveWm, gveWb,
                         geWh, geMu, geWm, geWb, out_e);
    k_node2<<<296, 256>>>(lng, lnb);
    k_scale<1><<<1, 1>>>();
    k_node3<<<1184, 256>>>(out);
}